// round 1
// baseline (speedup 1.0000x reference)
#include <cuda_runtime.h>
#include <math.h>
#include <stdint.h>

// Problem dims
#define NB 4096
#define NF 64
#define NE 16
#define NK 8
#define NO 32
#define NHID 1024
#define ND0 4096     // NK*NO*NE
#define NCH 256      // NK*NO
#define BNEPS 1e-5f

// ---------------- scratch (device globals; no allocation) ----------------
__device__ float  g_xe[(size_t)NB * NF * NE];     // 16 MB
__device__ float  g_xsum[NB * NE];                // xe summed over f
__device__ float  g_kq[NK * NO * NE];
__device__ double g_esum[NF], g_esq[NF];          // exp(xe) stats accumulators
__device__ float  g_escale[NF], g_eshift[NF];
__device__ float  g_arm[(size_t)NB * ND0];        // 64 MB
__device__ float  g_ascale[NCH], g_ashift[NCH];
__device__ float  g_z1[(size_t)NB * NHID];        // 16 MB
__device__ float  g_s1[NHID], g_sh1[NHID];
__device__ float  g_z2[(size_t)NB * NHID];        // 16 MB
__device__ float  g_s2[NHID], g_sh2[NHID];

// ---------------- helpers ----------------
__device__ __forceinline__ float segsum8(float v) {
    v += __shfl_xor_sync(0xffffffffu, v, 1);
    v += __shfl_xor_sync(0xffffffffu, v, 2);
    v += __shfl_xor_sync(0xffffffffu, v, 4);
    return v;
}
__device__ __forceinline__ float segmax8(float v) {
    v = fmaxf(v, __shfl_xor_sync(0xffffffffu, v, 1));
    v = fmaxf(v, __shfl_xor_sync(0xffffffffu, v, 2));
    v = fmaxf(v, __shfl_xor_sync(0xffffffffu, v, 4));
    return v;
}

// ---------------- kernels ----------------
__global__ void k_zero() {
    int t = threadIdx.x;
    if (t < NF) { g_esum[t] = 0.0; g_esq[t] = 0.0; }
}

// kq[k,o,x] = sum_y bil[k,x,y] * Q[k,o,y]
__global__ void k_kq(const float* __restrict__ bil, const float* __restrict__ Q) {
    int idx = blockIdx.x * 256 + threadIdx.x;   // 4096 total
    int k = idx >> 9;
    int rem = idx & 511;
    int o = rem >> 4;
    int x = rem & 15;
    const float* bp = bil + k * 256 + x * 16;
    const float* qp = Q + k * 512 + o * 16;
    float s = 0.f;
#pragma unroll
    for (int y = 0; y < 16; ++y) s += bp[y] * qp[y];
    g_kq[k * 512 + o * 16 + x] = s;
}

// per (b): xe = emb[id]*clip(v); write xe; xsum over f; exp stats per f (double atomics)
__global__ void k_embed(const int* __restrict__ x_id, const float* __restrict__ x_value,
                        const float* __restrict__ emb) {
    __shared__ float s[NF * 17];
    int b = blockIdx.x, f = threadIdx.x;
    float v = x_value[b * NF + f];
    v = fminf(fmaxf(v, 0.001f), 1.0f);
    long id = x_id[b * NF + f];
    const float4* er = (const float4*)(emb + (size_t)id * NE);
    float4 r[4];
    r[0] = er[0]; r[1] = er[1]; r[2] = er[2]; r[3] = er[3];
    float xv[16];
#pragma unroll
    for (int q = 0; q < 4; ++q) {
        xv[q * 4 + 0] = r[q].x * v; xv[q * 4 + 1] = r[q].y * v;
        xv[q * 4 + 2] = r[q].z * v; xv[q * 4 + 3] = r[q].w * v;
    }
    float4* dst = (float4*)(g_xe + (size_t)b * (NF * NE) + f * NE);
#pragma unroll
    for (int q = 0; q < 4; ++q)
        dst[q] = make_float4(xv[q * 4], xv[q * 4 + 1], xv[q * 4 + 2], xv[q * 4 + 3]);
    double es = 0.0, eq = 0.0;
#pragma unroll
    for (int x = 0; x < 16; ++x) {
        s[f * 17 + x] = xv[x];
        float e = expf(xv[x]);
        es += (double)e;
        eq += (double)e * (double)e;
    }
    atomicAdd(&g_esum[f], es);
    atomicAdd(&g_esq[f], eq);
    __syncthreads();
    if (f < NE) {
        float acc = 0.f;
#pragma unroll
        for (int rr = 0; rr < NF; ++rr) acc += s[rr * 17 + f];
        g_xsum[b * NE + f] = acc;
    }
}

__global__ void k_efinal(const float* __restrict__ emb_g, const float* __restrict__ emb_b) {
    int f = threadIdx.x;
    if (f >= NF) return;
    const double n = (double)NB * NE;
    double m = g_esum[f] / n;
    double var = g_esq[f] / n - m * m;
    if (var < 0.0) var = 0.0;
    float inv = (float)(1.0 / sqrt(var + (double)BNEPS));
    float sc = emb_g[f] * inv;
    g_escale[f] = sc;
    g_eshift[f] = emb_b[f] - (float)m * sc;
}

// main: per (b,k) block -> scores, entmax (50-iter bisection, faithful), arm
__global__ void __launch_bounds__(256) k_main(const float* __restrict__ vals_in) {
    __shared__ float s_xe[NF * 17];
    __shared__ float s_xp[NF * 17];
    __shared__ float s_kq[NO * NE];     // 512
    __shared__ float s_vals[NO * NF];   // 2048
    __shared__ float s_aw[NO * NF];     // 2048
    __shared__ float s_xsum[NE];

    int bid = blockIdx.x;
    int b = bid >> 3, k = bid & 7;
    int tid = threadIdx.x;

    { // load xe + normalized exp(xe)
        const float4* src = (const float4*)(g_xe + (size_t)b * (NF * NE));
        float4 v = src[tid];
        int f = tid >> 2;
        int x = (tid & 3) * 4;
        float sc = g_escale[f], sh = g_eshift[f];
        float* d = &s_xe[f * 17 + x];
        d[0] = v.x; d[1] = v.y; d[2] = v.z; d[3] = v.w;
        float* dp = &s_xp[f * 17 + x];
        dp[0] = fmaf(expf(v.x), sc, sh);
        dp[1] = fmaf(expf(v.y), sc, sh);
        dp[2] = fmaf(expf(v.z), sc, sh);
        dp[3] = fmaf(expf(v.w), sc, sh);
    }
    for (int i = tid; i < NO * NE; i += 256) s_kq[i] = g_kq[k * (NO * NE) + i];
    for (int i = tid; i < NO * NF; i += 256) s_vals[i] = vals_in[k * (NO * NF) + i];
    if (tid < NE) s_xsum[tid] = g_xsum[b * NE + tid];
    __syncthreads();

    int w = tid >> 5, l = tid & 31;
    int seg = l >> 3, il = l & 7;
    int o = (w << 2) + seg;   // 0..31

    float kqv[16];
#pragma unroll
    for (int x = 0; x < 16; ++x) kqv[x] = s_kq[o * 16 + x];
    float gc = 0.f;
#pragma unroll
    for (int x = 0; x < 16; ++x) gc += s_xsum[x] * kqv[x];

    float xs[8];
#pragma unroll
    for (int j = 0; j < 8; ++j) {
        int f = il + (j << 3);
        float d = 0.f;
#pragma unroll
        for (int x = 0; x < 16; ++x) d += s_xe[f * 17 + x] * kqv[x];
        xs[j] = 0.5f * (d + gc);
    }

    // entmax-1.5 bisection (faithful to reference: f_lo constant, 50 iters)
    float mx = xs[0];
#pragma unroll
    for (int j = 1; j < 8; ++j) mx = fmaxf(mx, xs[j]);
    mx = segmax8(mx);
    float tau_lo = mx - 1.0f;
    float fl = 0.f;
#pragma unroll
    for (int j = 0; j < 8; ++j) {
        float t = fmaxf(xs[j] - tau_lo, 0.f);
        fl += t * t;
    }
    fl = segsum8(fl) - 1.0f;
    float dm = 0.875f;              // tau_hi - tau_lo = 1 - sqrt(1/64)
    float tau_m = tau_lo;
#pragma unroll 1
    for (int it = 0; it < 50; ++it) {
        dm *= 0.5f;
        tau_m = tau_lo + dm;
        float fm = 0.f;
#pragma unroll
        for (int j = 0; j < 8; ++j) {
            float t = fmaxf(xs[j] - tau_m, 0.f);
            fm += t * t;
        }
        fm = segsum8(fm) - 1.0f;
        if (fm * fl >= 0.f) tau_lo = tau_m;
    }
    float p[8];
    float sp = 0.f;
#pragma unroll
    for (int j = 0; j < 8; ++j) {
        float t = fmaxf(xs[j] - tau_m, 0.f);
        p[j] = t * t;
        sp += p[j];
    }
    sp = segsum8(sp);
    float invp = 1.0f / sp;
#pragma unroll
    for (int j = 0; j < 8; ++j) {
        int f = il + (j << 3);
        s_aw[(o << 6) + f] = p[j] * invp * s_vals[(o << 6) + f];
    }
    __syncwarp();

    // arm[b, k*32+o, e] = sum_f x_exp[b,f,e] * aw[o,f]  (lane -> 2 e's)
    int e0 = il << 1;
    float a0 = 0.f, a1 = 0.f;
#pragma unroll
    for (int f = 0; f < NF; ++f) {
        float awf = s_aw[(o << 6) + f];
        a0 += s_xp[f * 17 + e0] * awf;
        a1 += s_xp[f * 17 + e0 + 1] * awf;
    }
    size_t base = (size_t)b * ND0 + (size_t)(k * NO + o) * NE + e0;
    g_arm[base] = a0;
    g_arm[base + 1] = a1;
}

// per-channel BN stats over (B,E) for arm
__global__ void k_armstats(const float* __restrict__ arm_g, const float* __restrict__ arm_b) {
    __shared__ double rs[256], rq[256];
    int c = blockIdx.x, tid = threadIdx.x;
    double s = 0.0, q = 0.0;
    for (int i = tid; i < NB * NE; i += 256) {
        int bb = i >> 4, e = i & 15;
        float v = g_arm[(size_t)bb * ND0 + c * NE + e];
        s += (double)v;
        q += (double)v * (double)v;
    }
    rs[tid] = s; rq[tid] = q;
    __syncthreads();
    for (int off = 128; off; off >>= 1) {
        if (tid < off) { rs[tid] += rs[tid + off]; rq[tid] += rq[tid + off]; }
        __syncthreads();
    }
    if (tid == 0) {
        const double n = (double)NB * NE;
        double m = rs[0] / n;
        double var = rq[0] / n - m * m;
        if (var < 0.0) var = 0.0;
        float inv = (float)(1.0 / sqrt(var + (double)BNEPS));
        float sc = arm_g[c] * inv;
        g_ascale[c] = sc;
        g_ashift[c] = arm_b[c] - (float)m * sc;
    }
}

// GEMM: Z[m,n] = sum_i norm(A[m,i]) * W[n,i] + bias[n]
// MODE 0: A=g_arm, channel=i>>4 scale/shift, no relu  -> g_z1  (K=4096)
// MODE 1: A=g_z1, per-i scale/shift + relu            -> g_z2  (K=1024)
template <int KDIM, int MODE>
__global__ void __launch_bounds__(256) k_gemm(const float* __restrict__ W,
                                              const float* __restrict__ bias) {
    const float* A     = (MODE == 0) ? g_arm   : g_z1;
    const float* scale = (MODE == 0) ? g_ascale : g_s1;
    const float* shift = (MODE == 0) ? g_ashift : g_sh1;
    float* Z           = (MODE == 0) ? g_z1    : g_z2;

    __shared__ float As[8 * 128];
    __shared__ float Bs[8 * 128];
    int tid = threadIdx.x;
    int tx = tid & 15, ty = tid >> 4;
    int m0 = blockIdx.x * 128, n0 = blockIdx.y * 128;
    int lr = tid >> 1;
    int lc = (tid & 1) * 4;
    const float* Aptr = A + (size_t)(m0 + lr) * KDIM + lc;
    const float* Wptr = W + (size_t)(n0 + lr) * KDIM + lc;

    float acc[8][8];
#pragma unroll
    for (int i = 0; i < 8; ++i)
#pragma unroll
        for (int j = 0; j < 8; ++j) acc[i][j] = 0.f;

    for (int k0 = 0; k0 < KDIM; k0 += 8) {
        float4 av = *(const float4*)(Aptr + k0);
        float4 wv = *(const float4*)(Wptr + k0);
        if (MODE == 0) {
            int ch = (k0 + lc) >> 4;
            float s = scale[ch], sh = shift[ch];
            av.x = fmaf(av.x, s, sh);
            av.y = fmaf(av.y, s, sh);
            av.z = fmaf(av.z, s, sh);
            av.w = fmaf(av.w, s, sh);
        } else {
            int i0 = k0 + lc;
            av.x = fmaxf(fmaf(av.x, scale[i0 + 0], shift[i0 + 0]), 0.f);
            av.y = fmaxf(fmaf(av.y, scale[i0 + 1], shift[i0 + 1]), 0.f);
            av.z = fmaxf(fmaf(av.z, scale[i0 + 2], shift[i0 + 2]), 0.f);
            av.w = fmaxf(fmaf(av.w, scale[i0 + 3], shift[i0 + 3]), 0.f);
        }
        __syncthreads();
        As[(lc + 0) * 128 + lr] = av.x;
        As[(lc + 1) * 128 + lr] = av.y;
        As[(lc + 2) * 128 + lr] = av.z;
        As[(lc + 3) * 128 + lr] = av.w;
        Bs[(lc + 0) * 128 + lr] = wv.x;
        Bs[(lc + 1) * 128 + lr] = wv.y;
        Bs[(lc + 2) * 128 + lr] = wv.z;
        Bs[(lc + 3) * 128 + lr] = wv.w;
        __syncthreads();
#pragma unroll
        for (int kk = 0; kk < 8; ++kk) {
            float4 a0 = *(const float4*)&As[kk * 128 + ty * 8];
            float4 a1 = *(const float4*)&As[kk * 128 + ty * 8 + 4];
            float4 b0 = *(const float4*)&Bs[kk * 128 + tx * 8];
            float4 b1 = *(const float4*)&Bs[kk * 128 + tx * 8 + 4];
            float am[8] = {a0.x, a0.y, a0.z, a0.w, a1.x, a1.y, a1.z, a1.w};
            float bn_[8] = {b0.x, b0.y, b0.z, b0.w, b1.x, b1.y, b1.z, b1.w};
#pragma unroll
            for (int i = 0; i < 8; ++i)
#pragma unroll
                for (int j = 0; j < 8; ++j) acc[i][j] += am[i] * bn_[j];
        }
    }
#pragma unroll
    for (int i = 0; i < 8; ++i) {
        int m = m0 + ty * 8 + i;
        float* zr = Z + (size_t)m * NHID + n0 + tx * 8;
#pragma unroll
        for (int j = 0; j < 8; ++j) zr[j] = acc[i][j] + bias[n0 + tx * 8 + j];
    }
}

// per-column BN stats over batch
template <int MODE>
__global__ void k_colstats(const float* __restrict__ g, const float* __restrict__ bt) {
    const float* Z = (MODE == 0) ? g_z1 : g_z2;
    float* sc = (MODE == 0) ? g_s1 : g_s2;
    float* sh = (MODE == 0) ? g_sh1 : g_sh2;
    __shared__ double rs[256], rq[256];
    int j = blockIdx.x, tid = threadIdx.x;
    double s = 0.0, q = 0.0;
    for (int bb = tid; bb < NB; bb += 256) {
        float v = Z[(size_t)bb * NHID + j];
        s += (double)v;
        q += (double)v * (double)v;
    }
    rs[tid] = s; rq[tid] = q;
    __syncthreads();
    for (int off = 128; off; off >>= 1) {
        if (tid < off) { rs[tid] += rs[tid + off]; rq[tid] += rq[tid + off]; }
        __syncthreads();
    }
    if (tid == 0) {
        double m = rs[0] * (1.0 / NB);
        double var = rq[0] * (1.0 / NB) - m * m;
        if (var < 0.0) var = 0.0;
        float inv = (float)(1.0 / sqrt(var + (double)BNEPS));
        float scv = g[j] * inv;
        sc[j] = scv;
        sh[j] = bt[j] - (float)m * scv;
    }
}

__global__ void k_final(const float* __restrict__ wout, const float* __restrict__ bout,
                        float* __restrict__ out) {
    __shared__ float r[128];
    int b = blockIdx.x, tid = threadIdx.x;
    float acc = 0.f;
    for (int j = tid; j < NHID; j += 128) {
        float h = fmaxf(fmaf(g_z2[(size_t)b * NHID + j], g_s2[j], g_sh2[j]), 0.f);
        acc += h * wout[j];
    }
    r[tid] = acc;
    __syncthreads();
    for (int off = 64; off; off >>= 1) {
        if (tid < off) r[tid] += r[tid + off];
        __syncthreads();
    }
    if (tid == 0) out[b] = r[0] + bout[0];
}

// ---------------- launch ----------------
extern "C" void kernel_launch(void* const* d_in, const int* in_sizes, int n_in,
                              void* d_out, int out_size) {
    const int*   x_id    = (const int*)d_in[0];
    const float* x_value = (const float*)d_in[1];
    const float* emb     = (const float*)d_in[2];
    const float* emb_g   = (const float*)d_in[3];
    const float* emb_b   = (const float*)d_in[4];
    const float* Q       = (const float*)d_in[5];
    const float* bil     = (const float*)d_in[6];
    const float* vals    = (const float*)d_in[7];
    const float* arm_g   = (const float*)d_in[8];
    const float* arm_b   = (const float*)d_in[9];
    const float* w1      = (const float*)d_in[10];
    const float* b1      = (const float*)d_in[11];
    const float* g1      = (const float*)d_in[12];
    const float* bt1     = (const float*)d_in[13];
    const float* w2      = (const float*)d_in[14];
    const float* b2      = (const float*)d_in[15];
    const float* g2      = (const float*)d_in[16];
    const float* bt2     = (const float*)d_in[17];
    const float* wout    = (const float*)d_in[18];
    const float* bout    = (const float*)d_in[19];
    float* out = (float*)d_out;

    k_zero<<<1, 64>>>();
    k_kq<<<16, 256>>>(bil, Q);
    k_embed<<<NB, NF>>>(x_id, x_value, emb);
    k_efinal<<<1, 64>>>(emb_g, emb_b);
    k_main<<<NB * NK, 256>>>(vals);
    k_armstats<<<NCH, 256>>>(arm_g, arm_b);
    k_gemm<ND0, 0><<<dim3(NB / 128, NHID / 128), 256>>>(w1, b1);
    k_colstats<0><<<NHID, 256>>>(g1, bt1);
    k_gemm<NHID, 1><<<dim3(NB / 128, NHID / 128), 256>>>(w2, b2);
    k_colstats<1><<<NHID, 256>>>(g2, bt2);
    k_final<<<NB, 128>>>(wout, bout, out);
}

// round 3
// speedup vs baseline: 1.0851x; 1.0851x over previous
#include <cuda_runtime.h>
#include <math.h>
#include <stdint.h>

// Problem dims
#define NB 4096
#define NF 64
#define NE 16
#define NK 8
#define NO 32
#define NHID 1024
#define ND0 4096     // NK*NO*NE
#define NCH 256      // NK*NO
#define BNEPS 1e-5f

// ---------------- scratch (device globals; no allocation) ----------------
__device__ float  g_xe[(size_t)NB * NF * NE];     // 16 MB
__device__ float  g_xsum[NB * NE];
__device__ float  g_kq[NK * NO * NE];
__device__ double g_esum[NF], g_esq[NF];
__device__ float  g_escale[NF], g_eshift[NF];
__device__ float  g_arm[(size_t)NB * ND0];        // 64 MB
__device__ float  g_ascale[NCH], g_ashift[NCH];
__device__ float  g_z1[(size_t)NB * NHID];        // 16 MB
__device__ float  g_s1[NHID], g_sh1[NHID];
__device__ float  g_z2[(size_t)NB * NHID];        // 16 MB
__device__ float  g_s2[NHID], g_sh2[NHID];

// ---------------- helpers ----------------
__device__ __forceinline__ float segsum8(float v) {
    v += __shfl_xor_sync(0xffffffffu, v, 1);
    v += __shfl_xor_sync(0xffffffffu, v, 2);
    v += __shfl_xor_sync(0xffffffffu, v, 4);
    return v;
}
__device__ __forceinline__ float segmax8(float v) {
    v = fmaxf(v, __shfl_xor_sync(0xffffffffu, v, 1));
    v = fmaxf(v, __shfl_xor_sync(0xffffffffu, v, 2));
    v = fmaxf(v, __shfl_xor_sync(0xffffffffu, v, 4));
    return v;
}
__device__ __forceinline__ uint32_t f2tf32(float x) {
    uint32_t r;
    asm("cvt.rna.tf32.f32 %0, %1;" : "=r"(r) : "f"(x));
    return r;
}
__device__ __forceinline__ void mma_tf32(float* d, float2 ar0, float2 ar1, float2 b) {
    asm volatile(
        "mma.sync.aligned.m16n8k8.row.col.f32.tf32.tf32.f32 "
        "{%0,%1,%2,%3}, {%4,%5,%6,%7}, {%8,%9}, {%0,%1,%2,%3};"
        : "+f"(d[0]), "+f"(d[1]), "+f"(d[2]), "+f"(d[3])
        : "r"(__float_as_uint(ar0.x)), "r"(__float_as_uint(ar1.x)),
          "r"(__float_as_uint(ar0.y)), "r"(__float_as_uint(ar1.y)),
          "r"(__float_as_uint(b.x)), "r"(__float_as_uint(b.y)));
}
// split x,y into tf32 hi/lo and store as adjacent pair (perm layout)
__device__ __forceinline__ void split_pair(float x, float y, float* hi, float* lo) {
    float h0 = __uint_as_float(f2tf32(x));
    float h1 = __uint_as_float(f2tf32(y));
    *(float2*)hi = make_float2(h0, h1);
    *(float2*)lo = make_float2(__uint_as_float(f2tf32(x - h0)),
                               __uint_as_float(f2tf32(y - h1)));
}

// ---------------- kernels ----------------
__global__ void k_zero() {
    int t = threadIdx.x;
    if (t < NF) { g_esum[t] = 0.0; g_esq[t] = 0.0; }
}

__global__ void k_kq(const float* __restrict__ bil, const float* __restrict__ Q) {
    int idx = blockIdx.x * 256 + threadIdx.x;
    int k = idx >> 9;
    int rem = idx & 511;
    int o = rem >> 4;
    int x = rem & 15;
    const float* bp = bil + k * 256 + x * 16;
    const float* qp = Q + k * 512 + o * 16;
    float s = 0.f;
#pragma unroll
    for (int y = 0; y < 16; ++y) s += bp[y] * qp[y];
    g_kq[k * 512 + o * 16 + x] = s;
}

__global__ void k_embed(const int* __restrict__ x_id, const float* __restrict__ x_value,
                        const float* __restrict__ emb) {
    __shared__ float s[NF * 17];
    int b = blockIdx.x, f = threadIdx.x;
    float v = x_value[b * NF + f];
    v = fminf(fmaxf(v, 0.001f), 1.0f);
    long id = x_id[b * NF + f];
    const float4* er = (const float4*)(emb + (size_t)id * NE);
    float4 r[4];
    r[0] = er[0]; r[1] = er[1]; r[2] = er[2]; r[3] = er[3];
    float xv[16];
#pragma unroll
    for (int q = 0; q < 4; ++q) {
        xv[q * 4 + 0] = r[q].x * v; xv[q * 4 + 1] = r[q].y * v;
        xv[q * 4 + 2] = r[q].z * v; xv[q * 4 + 3] = r[q].w * v;
    }
    float4* dst = (float4*)(g_xe + (size_t)b * (NF * NE) + f * NE);
#pragma unroll
    for (int q = 0; q < 4; ++q)
        dst[q] = make_float4(xv[q * 4], xv[q * 4 + 1], xv[q * 4 + 2], xv[q * 4 + 3]);
    double es = 0.0, eq = 0.0;
#pragma unroll
    for (int x = 0; x < 16; ++x) {
        s[f * 17 + x] = xv[x];
        float e = expf(xv[x]);
        es += (double)e;
        eq += (double)e * (double)e;
    }
    atomicAdd(&g_esum[f], es);
    atomicAdd(&g_esq[f], eq);
    __syncthreads();
    if (f < NE) {
        float acc = 0.f;
#pragma unroll
        for (int rr = 0; rr < NF; ++rr) acc += s[rr * 17 + f];
        g_xsum[b * NE + f] = acc;
    }
}

__global__ void k_efinal(const float* __restrict__ emb_g, const float* __restrict__ emb_b) {
    int f = threadIdx.x;
    if (f >= NF) return;
    const double n = (double)NB * NE;
    double m = g_esum[f] / n;
    double var = g_esq[f] / n - m * m;
    if (var < 0.0) var = 0.0;
    float inv = (float)(1.0 / sqrt(var + (double)BNEPS));
    float sc = emb_g[f] * inv;
    g_escale[f] = sc;
    g_eshift[f] = emb_b[f] - (float)m * sc;
}

__global__ void __launch_bounds__(256) k_main(const float* __restrict__ vals_in) {
    __shared__ float s_xe[NF * 17];
    __shared__ float s_xp[NF * 17];
    __shared__ float s_kq[NO * NE];
    __shared__ float s_vals[NO * NF];
    __shared__ float s_aw[NO * NF];
    __shared__ float s_xsum[NE];

    int bid = blockIdx.x;
    int b = bid >> 3, k = bid & 7;
    int tid = threadIdx.x;

    {
        const float4* src = (const float4*)(g_xe + (size_t)b * (NF * NE));
        float4 v = src[tid];
        int f = tid >> 2;
        int x = (tid & 3) * 4;
        float sc = g_escale[f], sh = g_eshift[f];
        float* d = &s_xe[f * 17 + x];
        d[0] = v.x; d[1] = v.y; d[2] = v.z; d[3] = v.w;
        float* dp = &s_xp[f * 17 + x];
        dp[0] = fmaf(expf(v.x), sc, sh);
        dp[1] = fmaf(expf(v.y), sc, sh);
        dp[2] = fmaf(expf(v.z), sc, sh);
        dp[3] = fmaf(expf(v.w), sc, sh);
    }
    for (int i = tid; i < NO * NE; i += 256) s_kq[i] = g_kq[k * (NO * NE) + i];
    for (int i = tid; i < NO * NF; i += 256) s_vals[i] = vals_in[k * (NO * NF) + i];
    if (tid < NE) s_xsum[tid] = g_xsum[b * NE + tid];
    __syncthreads();

    int w = tid >> 5, l = tid & 31;
    int seg = l >> 3, il = l & 7;
    int o = (w << 2) + seg;

    float kqv[16];
#pragma unroll
    for (int x = 0; x < 16; ++x) kqv[x] = s_kq[o * 16 + x];
    float gc = 0.f;
#pragma unroll
    for (int x = 0; x < 16; ++x) gc += s_xsum[x] * kqv[x];

    float xs[8];
#pragma unroll
    for (int j = 0; j < 8; ++j) {
        int f = il + (j << 3);
        float d = 0.f;
#pragma unroll
        for (int x = 0; x < 16; ++x) d += s_xe[f * 17 + x] * kqv[x];
        xs[j] = 0.5f * (d + gc);
    }

    // entmax-1.5 bisection (faithful; early-break when f32-saturated — bitwise no-op after)
    float mx = xs[0];
#pragma unroll
    for (int j = 1; j < 8; ++j) mx = fmaxf(mx, xs[j]);
    mx = segmax8(mx);
    float tau_lo = mx - 1.0f;
    float fl = 0.f;
#pragma unroll
    for (int j = 0; j < 8; ++j) {
        float t = fmaxf(xs[j] - tau_lo, 0.f);
        fl += t * t;
    }
    fl = segsum8(fl) - 1.0f;
    float dm = 0.875f;
    float tau_m = tau_lo;
#pragma unroll 1
    for (int it = 0; it < 50; ++it) {
        dm *= 0.5f;
        tau_m = tau_lo + dm;
        if (__all_sync(0xffffffffu, tau_m == tau_lo)) break;
        float fm = 0.f;
#pragma unroll
        for (int j = 0; j < 8; ++j) {
            float t = fmaxf(xs[j] - tau_m, 0.f);
            fm += t * t;
        }
        fm = segsum8(fm) - 1.0f;
        if (fm * fl >= 0.f) tau_lo = tau_m;
    }
    float p[8];
    float sp = 0.f;
#pragma unroll
    for (int j = 0; j < 8; ++j) {
        float t = fmaxf(xs[j] - tau_m, 0.f);
        p[j] = t * t;
        sp += p[j];
    }
    sp = segsum8(sp);
    float invp = 1.0f / sp;
#pragma unroll
    for (int j = 0; j < 8; ++j) {
        int f = il + (j << 3);
        s_aw[(o << 6) + f] = p[j] * invp * s_vals[(o << 6) + f];
    }
    __syncwarp();

    int e0 = il << 1;
    float a0 = 0.f, a1 = 0.f;
#pragma unroll
    for (int f = 0; f < NF; ++f) {
        float awf = s_aw[(o << 6) + f];
        a0 += s_xp[f * 17 + e0] * awf;
        a1 += s_xp[f * 17 + e0 + 1] * awf;
    }
    size_t base = (size_t)b * ND0 + (size_t)(k * NO + o) * NE + e0;
    g_arm[base] = a0;
    g_arm[base + 1] = a1;
}

__global__ void k_armstats(const float* __restrict__ arm_g, const float* __restrict__ arm_b) {
    __shared__ double rs[256], rq[256];
    int c = blockIdx.x, tid = threadIdx.x;
    double s = 0.0, q = 0.0;
    for (int i = tid; i < NB * NE; i += 256) {
        int bb = i >> 4, e = i & 15;
        float v = g_arm[(size_t)bb * ND0 + c * NE + e];
        s += (double)v;
        q += (double)v * (double)v;
    }
    rs[tid] = s; rq[tid] = q;
    __syncthreads();
    for (int off = 128; off; off >>= 1) {
        if (tid < off) { rs[tid] += rs[tid + off]; rq[tid] += rq[tid + off]; }
        __syncthreads();
    }
    if (tid == 0) {
        const double n = (double)NB * NE;
        double m = rs[0] / n;
        double var = rq[0] / n - m * m;
        if (var < 0.0) var = 0.0;
        float inv = (float)(1.0 / sqrt(var + (double)BNEPS));
        float sc = arm_g[c] * inv;
        g_ascale[c] = sc;
        g_ashift[c] = arm_b[c] - (float)m * sc;
    }
}

// ---------- TF32 tensor-core GEMM (3-term split: hi*hi + lo*hi + hi*lo) ----------
// Z[m,n] = sum_i norm(A[m,i]) * W[n,i] + bias[n]
template <int KDIM, int MODE>
__global__ void __launch_bounds__(256) k_gemm(const float* __restrict__ W,
                                              const float* __restrict__ bias) {
    const float* A     = (MODE == 0) ? g_arm    : g_z1;
    const float* scale = (MODE == 0) ? g_ascale : g_s1;
    const float* shift = (MODE == 0) ? g_ashift : g_sh1;
    float* Z           = (MODE == 0) ? g_z1     : g_z2;

    // perm layout: slot 2c holds col c, slot 2c+1 holds col c+4 (per k8 chunk)
    __shared__ float Ah[2][128][10], Alo[2][128][10];
    __shared__ float Bh[2][128][10], Blo[2][128][10];

    int tid = threadIdx.x;
    int m0 = blockIdx.x * 128, n0 = blockIdx.y * 128;
    int row = tid >> 1, half = tid & 1;
    const float* Ag = A + (size_t)(m0 + row) * KDIM + half * 8;
    const float* Wg = W + (size_t)(n0 + row) * KDIM + half * 8;

    float4 ra0, ra1, rb0, rb1;

#define LOAD_STAGE(kk)                                                         \
    {                                                                          \
        ra0 = *(const float4*)(Ag + (kk));                                     \
        ra1 = *(const float4*)(Ag + (kk) + 4);                                 \
        rb0 = *(const float4*)(Wg + (kk));                                     \
        rb1 = *(const float4*)(Wg + (kk) + 4);                                 \
        if (MODE == 0) {                                                       \
            float s_ = scale[(kk) >> 4], h_ = shift[(kk) >> 4];                \
            ra0.x = fmaf(ra0.x, s_, h_); ra0.y = fmaf(ra0.y, s_, h_);          \
            ra0.z = fmaf(ra0.z, s_, h_); ra0.w = fmaf(ra0.w, s_, h_);          \
            ra1.x = fmaf(ra1.x, s_, h_); ra1.y = fmaf(ra1.y, s_, h_);          \
            ra1.z = fmaf(ra1.z, s_, h_); ra1.w = fmaf(ra1.w, s_, h_);          \
        } else {                                                               \
            int i0_ = (kk) + half * 8;                                         \
            ra0.x = fmaxf(fmaf(ra0.x, scale[i0_ + 0], shift[i0_ + 0]), 0.f);   \
            ra0.y = fmaxf(fmaf(ra0.y, scale[i0_ + 1], shift[i0_ + 1]), 0.f);   \
            ra0.z = fmaxf(fmaf(ra0.z, scale[i0_ + 2], shift[i0_ + 2]), 0.f);   \
            ra0.w = fmaxf(fmaf(ra0.w, scale[i0_ + 3], shift[i0_ + 3]), 0.f);   \
            ra1.x = fmaxf(fmaf(ra1.x, scale[i0_ + 4], shift[i0_ + 4]), 0.f);   \
            ra1.y = fmaxf(fmaf(ra1.y, scale[i0_ + 5], shift[i0_ + 5]), 0.f);   \
            ra1.z = fmaxf(fmaf(ra1.z, scale[i0_ + 6], shift[i0_ + 6]), 0.f);   \
            ra1.w = fmaxf(fmaf(ra1.w, scale[i0_ + 7], shift[i0_ + 7]), 0.f);   \
        }                                                                      \
    }

#define STORE_STAGE()                                                          \
    {                                                                          \
        split_pair(ra0.x, ra1.x, &Ah[half][row][0], &Alo[half][row][0]);       \
        split_pair(ra0.y, ra1.y, &Ah[half][row][2], &Alo[half][row][2]);       \
        split_pair(ra0.z, ra1.z, &Ah[half][row][4], &Alo[half][row][4]);       \
        split_pair(ra0.w, ra1.w, &Ah[half][row][6], &Alo[half][row][6]);       \
        split_pair(rb0.x, rb1.x, &Bh[half][row][0], &Blo[half][row][0]);       \
        split_pair(rb0.y, rb1.y, &Bh[half][row][2], &Blo[half][row][2]);       \
        split_pair(rb0.z, rb1.z, &Bh[half][row][4], &Blo[half][row][4]);       \
        split_pair(rb0.w, rb1.w, &Bh[half][row][6], &Blo[half][row][6]);       \
    }

    LOAD_STAGE(0);
    STORE_STAGE();
    __syncthreads();

    float acc[2][8][4];
#pragma unroll
    for (int mt = 0; mt < 2; ++mt)
#pragma unroll
        for (int nt = 0; nt < 8; ++nt)
#pragma unroll
            for (int q = 0; q < 4; ++q) acc[mt][nt][q] = 0.f;

    int lane = tid & 31, warp = tid >> 5;
    int mb = (warp >> 1) * 32, nb = (warp & 1) * 64;
    int g = lane >> 2, t4 = lane & 3;

    for (int k0 = 0; k0 < KDIM; k0 += 16) {
        bool more = (k0 + 16) < KDIM;
        if (more) LOAD_STAGE(k0 + 16);
#pragma unroll
        for (int ch = 0; ch < 2; ++ch) {
            float2 ah0[2], ah1[2], al0[2], al1[2];
#pragma unroll
            for (int mt = 0; mt < 2; ++mt) {
                int r = mb + mt * 16 + g;
                ah0[mt] = *(const float2*)&Ah[ch][r][t4 * 2];
                ah1[mt] = *(const float2*)&Ah[ch][r + 8][t4 * 2];
                al0[mt] = *(const float2*)&Alo[ch][r][t4 * 2];
                al1[mt] = *(const float2*)&Alo[ch][r + 8][t4 * 2];
            }
#pragma unroll
            for (int nt = 0; nt < 8; ++nt) {
                int n = nb + nt * 8 + g;
                float2 bhv = *(const float2*)&Bh[ch][n][t4 * 2];
                float2 blv = *(const float2*)&Blo[ch][n][t4 * 2];
#pragma unroll
                for (int mt = 0; mt < 2; ++mt) {
                    mma_tf32(acc[mt][nt], ah0[mt], ah1[mt], bhv);
                    mma_tf32(acc[mt][nt], al0[mt], al1[mt], bhv);
                    mma_tf32(acc[mt][nt], ah0[mt], ah1[mt], blv);
                }
            }
        }
        __syncthreads();
        if (more) {
            STORE_STAGE();
            __syncthreads();
        }
    }

#pragma unroll
    for (int mt = 0; mt < 2; ++mt) {
        int r = m0 + mb + mt * 16 + g;
#pragma unroll
        for (int nt = 0; nt < 8; ++nt) {
            int n = n0 + nb + nt * 8 + t4 * 2;
            float b0v = bias[n], b1v = bias[n + 1];
            *(float2*)(Z + (size_t)r * NHID + n) =
                make_float2(acc[mt][nt][0] + b0v, acc[mt][nt][1] + b1v);
            *(float2*)(Z + (size_t)(r + 8) * NHID + n) =
                make_float2(acc[mt][nt][2] + b0v, acc[mt][nt][3] + b1v);
        }
    }
#undef LOAD_STAGE
#undef STORE_STAGE
}

// per-column BN stats over batch, coalesced (warp covers 32 consecutive columns)
template <int MODE>
__global__ void k_colstats(const float* __restrict__ g, const float* __restrict__ bt) {
    const float* Z = (MODE == 0) ? g_z1 : g_z2;
    float* sc = (MODE == 0) ? g_s1 : g_s2;
    float* sh = (MODE == 0) ? g_sh1 : g_sh2;
    __shared__ double rs[8][32], rq[8][32];
    int tid = threadIdx.x;
    int col = blockIdx.x * 32 + (tid & 31);
    int part = tid >> 5;
    double s = 0.0, q = 0.0;
    for (int bb = part * 512; bb < part * 512 + 512; ++bb) {
        float v = Z[(size_t)bb * NHID + col];
        s += (double)v;
        q += (double)v * (double)v;
    }
    rs[part][tid & 31] = s;
    rq[part][tid & 31] = q;
    __syncthreads();
    if (part == 0) {
        double S = 0.0, Q2 = 0.0;
#pragma unroll
        for (int p2 = 0; p2 < 8; ++p2) { S += rs[p2][tid]; Q2 += rq[p2][tid]; }
        double m = S * (1.0 / NB);
        double var = Q2 * (1.0 / NB) - m * m;
        if (var < 0.0) var = 0.0;
        float inv = (float)(1.0 / sqrt(var + (double)BNEPS));
        float scv = g[col] * inv;
        sc[col] = scv;
        sh[col] = bt[col] - (float)m * scv;
    }
}

__global__ void k_final(const float* __restrict__ wout, const float* __restrict__ bout,
                        float* __restrict__ out) {
    __shared__ float r[128];
    int b = blockIdx.x, tid = threadIdx.x;
    float acc = 0.f;
    for (int j = tid; j < NHID; j += 128) {
        float h = fmaxf(fmaf(g_z2[(size_t)b * NHID + j], g_s2[j], g_sh2[j]), 0.f);
        acc += h * wout[j];
    }
    r[tid] = acc;
    __syncthreads();
    for (int off = 64; off; off >>= 1) {
        if (tid < off) r[tid] += r[tid + off];
        __syncthreads();
    }
    if (tid == 0) out[b] = r[0] + bout[0];
}

// ---------------- launch ----------------
extern "C" void kernel_launch(void* const* d_in, const int* in_sizes, int n_in,
                              void* d_out, int out_size) {
    const int*   x_id    = (const int*)d_in[0];
    const float* x_value = (const float*)d_in[1];
    const float* emb     = (const float*)d_in[2];
    const float* emb_g   = (const float*)d_in[3];
    const float* emb_b   = (const float*)d_in[4];
    const float* Q       = (const float*)d_in[5];
    const float* bil     = (const float*)d_in[6];
    const float* vals    = (const float*)d_in[7];
    const float* arm_g   = (const float*)d_in[8];
    const float* arm_b   = (const float*)d_in[9];
    const float* w1      = (const float*)d_in[10];
    const float* b1      = (const float*)d_in[11];
    const float* g1      = (const float*)d_in[12];
    const float* bt1     = (const float*)d_in[13];
    const float* w2      = (const float*)d_in[14];
    const float* b2      = (const float*)d_in[15];
    const float* g2      = (const float*)d_in[16];
    const float* bt2     = (const float*)d_in[17];
    const float* wout    = (const float*)d_in[18];
    const float* bout    = (const float*)d_in[19];
    float* out = (float*)d_out;

    k_zero<<<1, 64>>>();
    k_kq<<<16, 256>>>(bil, Q);
    k_embed<<<NB, NF>>>(x_id, x_value, emb);
    k_efinal<<<1, 64>>>(emb_g, emb_b);
    k_main<<<NB * NK, 256>>>(vals);
    k_armstats<<<NCH, 256>>>(arm_g, arm_b);
    k_gemm<ND0, 0><<<dim3(NB / 128, NHID / 128), 256>>>(w1, b1);
    k_colstats<0><<<NHID / 32, 256>>>(g1, bt1);
    k_gemm<NHID, 1><<<dim3(NB / 128, NHID / 128), 256>>>(w2, b2);
    k_colstats<1><<<NHID / 32, 256>>>(g2, bt2);
    k_final<<<NB, 128>>>(wout, bout, out);
}

// round 10
// speedup vs baseline: 1.1031x; 1.0166x over previous
#include <cuda_runtime.h>
#include <math.h>
#include <stdint.h>

// Problem dims
#define NB 4096
#define NF 64
#define NE 16
#define NK 8
#define NO 32
#define NHID 1024
#define ND0 4096     // NK*NO*NE
#define NCH 256      // NK*NO
#define BNEPS 1e-5f

// ---------------- scratch (device globals; no allocation) ----------------
__device__ __align__(256) float  g_xe[(size_t)NB * NF * NE];     // 16 MB
__device__ __align__(256) float  g_xsum[NB * NE];
__device__ __align__(256) float  g_kq[NK * NO * NE];
__device__ __align__(256) double g_esum[NF];
__device__ __align__(256) double g_esq[NF];
__device__ __align__(256) float  g_escale[NF];
__device__ __align__(256) float  g_eshift[NF];
__device__ __align__(256) float  g_arm[(size_t)NB * ND0];        // 64 MB
__device__ __align__(256) float  g_ascale[NCH];
__device__ __align__(256) float  g_ashift[NCH];
__device__ __align__(256) float  g_z1[(size_t)NB * NHID];        // 16 MB
__device__ __align__(256) float  g_s1[NHID];
__device__ __align__(256) float  g_sh1[NHID];
__device__ __align__(256) float  g_z2[(size_t)NB * NHID];        // 16 MB
__device__ __align__(256) float  g_s2[NHID];
__device__ __align__(256) float  g_sh2[NHID];

// ---------------- helpers ----------------
__device__ __forceinline__ float segsum8(float v) {
    v += __shfl_xor_sync(0xffffffffu, v, 1);
    v += __shfl_xor_sync(0xffffffffu, v, 2);
    v += __shfl_xor_sync(0xffffffffu, v, 4);
    return v;
}
__device__ __forceinline__ float segmax8(float v) {
    v = fmaxf(v, __shfl_xor_sync(0xffffffffu, v, 1));
    v = fmaxf(v, __shfl_xor_sync(0xffffffffu, v, 2));
    v = fmaxf(v, __shfl_xor_sync(0xffffffffu, v, 4));
    return v;
}
__device__ __forceinline__ float tf32_rna(float x) {
    uint32_t r;
    asm("cvt.rna.tf32.f32 %0, %1;" : "=r"(r) : "f"(x));
    return __uint_as_float(r);
}
__device__ __forceinline__ void mma8(float* d, float a0, float a1, float a2, float a3,
                                     float b0, float b1) {
    asm volatile(
        "mma.sync.aligned.m16n8k8.row.col.f32.tf32.tf32.f32 "
        "{%0,%1,%2,%3}, {%4,%5,%6,%7}, {%8,%9}, {%0,%1,%2,%3};"
        : "+f"(d[0]), "+f"(d[1]), "+f"(d[2]), "+f"(d[3])
        : "r"(__float_as_uint(a0)), "r"(__float_as_uint(a1)),
          "r"(__float_as_uint(a2)), "r"(__float_as_uint(a3)),
          "r"(__float_as_uint(b0)), "r"(__float_as_uint(b1)));
}

// ---------------- kernels ----------------
__global__ void k_zero() {
    int t = threadIdx.x;
    if (t < NF) { g_esum[t] = 0.0; g_esq[t] = 0.0; }
}

// per (b): xe = emb[id]*clip(v); write xe; xsum over f; exp stats per f (double atomics)
__global__ void k_embed(const int* __restrict__ x_id, const float* __restrict__ x_value,
                        const float* __restrict__ emb) {
    __shared__ float s[NF * 17];
    int b = blockIdx.x, f = threadIdx.x;
    float v = x_value[b * NF + f];
    v = fminf(fmaxf(v, 0.001f), 1.0f);
    long id = x_id[b * NF + f];
    const float4* er = (const float4*)(emb + (size_t)id * NE);
    float4 r[4];
    r[0] = er[0]; r[1] = er[1]; r[2] = er[2]; r[3] = er[3];
    float xv[16];
#pragma unroll
    for (int q = 0; q < 4; ++q) {
        xv[q * 4 + 0] = r[q].x * v; xv[q * 4 + 1] = r[q].y * v;
        xv[q * 4 + 2] = r[q].z * v; xv[q * 4 + 3] = r[q].w * v;
    }
    float4* dst = (float4*)(g_xe + (size_t)b * (NF * NE) + f * NE);
#pragma unroll
    for (int q = 0; q < 4; ++q)
        dst[q] = make_float4(xv[q * 4], xv[q * 4 + 1], xv[q * 4 + 2], xv[q * 4 + 3]);
    double es = 0.0, eq = 0.0;
#pragma unroll
    for (int x = 0; x < 16; ++x) {
        s[f * 17 + x] = xv[x];
        float e = expf(xv[x]);
        es += (double)e;
        eq += (double)e * (double)e;
    }
    atomicAdd(&g_esum[f], es);
    atomicAdd(&g_esq[f], eq);
    __syncthreads();
    if (f < NE) {
        float acc = 0.f;
#pragma unroll
        for (int rr = 0; rr < NF; ++rr) acc += s[rr * 17 + f];
        g_xsum[b * NE + f] = acc;
    }
}

// kq[k,o,x] = sum_y bil[k,x,y]*Q[k,o,y]; block 0 also finalizes exp-BN coefficients
__global__ void k_kqef(const float* __restrict__ bil, const float* __restrict__ Q,
                       const float* __restrict__ emb_g, const float* __restrict__ emb_b) {
    int idx = blockIdx.x * 256 + threadIdx.x;
    int k = idx >> 9;
    int rem = idx & 511;
    int o = rem >> 4;
    int x = rem & 15;
    const float* bp = bil + k * 256 + x * 16;
    const float* qp = Q + k * 512 + o * 16;
    float s = 0.f;
#pragma unroll
    for (int y = 0; y < 16; ++y) s += bp[y] * qp[y];
    g_kq[k * 512 + o * 16 + x] = s;
    if (blockIdx.x == 0 && threadIdx.x < NF) {
        int f = threadIdx.x;
        const double n = (double)NB * NE;
        double m = g_esum[f] / n;
        double var = g_esq[f] / n - m * m;
        if (var < 0.0) var = 0.0;
        float inv = (float)(1.0 / sqrt(var + (double)BNEPS));
        float sc = emb_g[f] * inv;
        g_escale[f] = sc;
        g_eshift[f] = emb_b[f] - (float)m * sc;
    }
}

// main: per (b,k): scores -> entmax-1.5 (Newton on convex decreasing f) -> arm
__global__ void __launch_bounds__(256) k_main(const float* __restrict__ vals_in) {
    __shared__ float s_xe[NF * 17];
    __shared__ float s_xp[NF * 17];
    __shared__ float s_kq[NO * NE];
    __shared__ float s_vals[NO * NF];
    __shared__ float s_aw[NO * NF];
    __shared__ float s_xsum[NE];

    int bid = blockIdx.x;
    int b = bid >> 3, k = bid & 7;
    int tid = threadIdx.x;

    {
        const float4* src = (const float4*)(g_xe + (size_t)b * (NF * NE));
        float4 v = src[tid];
        int f = tid >> 2;
        int x = (tid & 3) * 4;
        float sc = g_escale[f], sh = g_eshift[f];
        float* d = &s_xe[f * 17 + x];
        d[0] = v.x; d[1] = v.y; d[2] = v.z; d[3] = v.w;
        float* dp = &s_xp[f * 17 + x];
        dp[0] = fmaf(expf(v.x), sc, sh);
        dp[1] = fmaf(expf(v.y), sc, sh);
        dp[2] = fmaf(expf(v.z), sc, sh);
        dp[3] = fmaf(expf(v.w), sc, sh);
    }
    for (int i = tid; i < NO * NE; i += 256) s_kq[i] = g_kq[k * (NO * NE) + i];
    for (int i = tid; i < NO * NF; i += 256) s_vals[i] = vals_in[k * (NO * NF) + i];
    if (tid < NE) s_xsum[tid] = g_xsum[b * NE + tid];
    __syncthreads();

    int w = tid >> 5, l = tid & 31;
    int seg = l >> 3, il = l & 7;
    int o = (w << 2) + seg;

    float kqv[16];
#pragma unroll
    for (int x = 0; x < 16; ++x) kqv[x] = s_kq[o * 16 + x];
    float gc = 0.f;
#pragma unroll
    for (int x = 0; x < 16; ++x) gc += s_xsum[x] * kqv[x];

    float xs[8];
#pragma unroll
    for (int j = 0; j < 8; ++j) {
        int f = il + (j << 3);
        float d = 0.f;
#pragma unroll
        for (int x = 0; x < 16; ++x) d += s_xe[f * 17 + x] * kqv[x];
        xs[j] = 0.5f * (d + gc);
    }

    // entmax-1.5 tau: Newton from tau0 = mx-1 (monotone from below on the convex
    // decreasing g(tau)=sum relu(xs-tau)^2 - 1; same f32-converged root as the
    // reference's 50 bisections). s1 >= 1 always (max element contributes 1 at tau0).
    float mx = xs[0];
#pragma unroll
    for (int j = 1; j < 8; ++j) mx = fmaxf(mx, xs[j]);
    mx = segmax8(mx);
    float tau = mx - 1.0f;
#pragma unroll 1
    for (int it = 0; it < 8; ++it) {
        float s1 = 0.f, s2 = 0.f;
#pragma unroll
        for (int j = 0; j < 8; ++j) {
            float t = fmaxf(xs[j] - tau, 0.f);
            s1 += t;
            s2 = fmaf(t, t, s2);
        }
        s1 = segsum8(s1);
        s2 = segsum8(s2);
        tau += (s2 - 1.0f) / (2.0f * s1);
    }
    float p[8];
    float sp = 0.f;
#pragma unroll
    for (int j = 0; j < 8; ++j) {
        float t = fmaxf(xs[j] - tau, 0.f);
        p[j] = t * t;
        sp += p[j];
    }
    sp = segsum8(sp);
    float invp = 1.0f / sp;
#pragma unroll
    for (int j = 0; j < 8; ++j) {
        int f = il + (j << 3);
        s_aw[(o << 6) + f] = p[j] * invp * s_vals[(o << 6) + f];
    }
    __syncwarp();

    int e0 = il << 1;
    float a0 = 0.f, a1 = 0.f;
#pragma unroll
    for (int f = 0; f < NF; ++f) {
        float awf = s_aw[(o << 6) + f];
        a0 += s_xp[f * 17 + e0] * awf;
        a1 += s_xp[f * 17 + e0 + 1] * awf;
    }
    size_t base = (size_t)b * ND0 + (size_t)(k * NO + o) * NE + e0;
    g_arm[base] = a0;
    g_arm[base + 1] = a1;
}

__global__ void k_armstats(const float* __restrict__ arm_g, const float* __restrict__ arm_b) {
    __shared__ double rs[256], rq[256];
    int c = blockIdx.x, tid = threadIdx.x;
    double s = 0.0, q = 0.0;
    for (int i = tid; i < NB * NE; i += 256) {
        int bb = i >> 4, e = i & 15;
        float v = g_arm[(size_t)bb * ND0 + c * NE + e];
        s += (double)v;
        q += (double)v * (double)v;
    }
    rs[tid] = s; rq[tid] = q;
    __syncthreads();
    for (int off = 128; off; off >>= 1) {
        if (tid < off) { rs[tid] += rs[tid + off]; rq[tid] += rq[tid + off]; }
        __syncthreads();
    }
    if (tid == 0) {
        const double n = (double)NB * NE;
        double m = rs[0] / n;
        double var = rq[0] / n - m * m;
        if (var < 0.0) var = 0.0;
        float inv = (float)(1.0 / sqrt(var + (double)BNEPS));
        float sc = arm_g[c] * inv;
        g_ascale[c] = sc;
        g_ashift[c] = arm_b[c] - (float)m * sc;
    }
}

// ---------- TF32 mma.sync GEMM, packed hi/lo quads, double buffer ----------
// Z[m,n] = sum_i norm(A[m,i]) * W[n,i] + bias[n]   (3xTF32: hh + lh + hl)
// smem layout (floats): stage s @ s*10240:
//   A chunk c (c=0,1 within k16) @ c*2560, B chunk c @ 5120 + c*2560
//   per row (128 rows): 20 floats (16 data + 4 pad); quad t4 at row*20 + t4*4 =
//   (hi[t4], hi[t4+4], lo[t4], lo[t4+4])
#define GM_STAGE 10240   // floats per stage
#define GM_SMEMB (2 * GM_STAGE * 4)

template <int KDIM, int MODE>
__global__ void __launch_bounds__(256, 1) k_gemm(const float* __restrict__ W,
                                                 const float* __restrict__ bias) {
    const float* A = (MODE == 0) ? g_arm : g_z1;
    float* Z       = (MODE == 0) ? g_z1  : g_z2;
    extern __shared__ __align__(16) float sm[];

    int tid = threadIdx.x;
    int row = tid & 127, chunk = tid >> 7;     // this thread's load unit
    int m0 = blockIdx.x * 128, n0 = blockIdx.y * 128;
    const float* Ag = A + (size_t)(m0 + row) * KDIM + chunk * 8;
    const float* Wg = W + (size_t)(n0 + row) * KDIM + chunk * 8;
    float* sArow = sm + chunk * 2560 + row * 20;
    float* sBrow = sm + 5120 + chunk * 2560 + row * 20;

    int warp = tid >> 5, lane = tid & 31, g = lane >> 2, t4 = lane & 3;
    int mb = (warp >> 1) * 32, nb = (warp & 1) * 64;

    float acc[2][8][4];
#pragma unroll
    for (int mt = 0; mt < 2; ++mt)
#pragma unroll
        for (int nt = 0; nt < 8; ++nt)
#pragma unroll
            for (int q = 0; q < 4; ++q) acc[mt][nt][q] = 0.f;

    float av[8], bv[8];

#define GM_LOAD(k0)                                                            \
    {                                                                          \
        float4 a0_ = *(const float4*)(Ag + (k0));                              \
        float4 a1_ = *(const float4*)(Ag + (k0) + 4);                          \
        float4 b0_ = *(const float4*)(Wg + (k0));                              \
        float4 b1_ = *(const float4*)(Wg + (k0) + 4);                          \
        av[0] = a0_.x; av[1] = a0_.y; av[2] = a0_.z; av[3] = a0_.w;            \
        av[4] = a1_.x; av[5] = a1_.y; av[6] = a1_.z; av[7] = a1_.w;            \
        bv[0] = b0_.x; bv[1] = b0_.y; bv[2] = b0_.z; bv[3] = b0_.w;            \
        bv[4] = b1_.x; bv[5] = b1_.y; bv[6] = b1_.z; bv[7] = b1_.w;            \
        if (MODE == 0) {                                                       \
            float s_ = g_ascale[(k0) >> 4], h_ = g_ashift[(k0) >> 4];          \
            _Pragma("unroll") for (int j = 0; j < 8; ++j)                      \
                av[j] = fmaf(av[j], s_, h_);                                   \
        } else {                                                               \
            int i0_ = (k0) + chunk * 8;                                        \
            float4 sc0 = *(const float4*)(g_s1 + i0_);                         \
            float4 sc1 = *(const float4*)(g_s1 + i0_ + 4);                     \
            float4 sh0 = *(const float4*)(g_sh1 + i0_);                        \
            float4 sh1 = *(const float4*)(g_sh1 + i0_ + 4);                    \
            av[0] = fmaxf(fmaf(av[0], sc0.x, sh0.x), 0.f);                     \
            av[1] = fmaxf(fmaf(av[1], sc0.y, sh0.y), 0.f);                     \
            av[2] = fmaxf(fmaf(av[2], sc0.z, sh0.z), 0.f);                     \
            av[3] = fmaxf(fmaf(av[3], sc0.w, sh0.w), 0.f);                     \
            av[4] = fmaxf(fmaf(av[4], sc1.x, sh1.x), 0.f);                     \
            av[5] = fmaxf(fmaf(av[5], sc1.y, sh1.y), 0.f);                     \
            av[6] = fmaxf(fmaf(av[6], sc1.z, sh1.z), 0.f);                     \
            av[7] = fmaxf(fmaf(av[7], sc1.w, sh1.w), 0.f);                     \
        }                                                                      \
    }

#define GM_STORE(st)                                                           \
    {                                                                          \
        int sb_ = (st) * GM_STAGE;                                             \
        _Pragma("unroll") for (int q = 0; q < 4; ++q) {                        \
            float ah = tf32_rna(av[q]);                                        \
            float ah4 = tf32_rna(av[q + 4]);                                   \
            float4 qa = make_float4(ah, ah4, tf32_rna(av[q] - ah),             \
                                    tf32_rna(av[q + 4] - ah4));                \
            *(float4*)(sArow + sb_ + q * 4) = qa;                              \
            float bh = tf32_rna(bv[q]);                                        \
            float bh4 = tf32_rna(bv[q + 4]);                                   \
            float4 qb = make_float4(bh, bh4, tf32_rna(bv[q] - bh),             \
                                    tf32_rna(bv[q + 4] - bh4));                \
            *(float4*)(sBrow + sb_ + q * 4) = qb;                              \
        }                                                                      \
    }

    GM_LOAD(0);
    GM_STORE(0);
    __syncthreads();

    const int NIT = KDIM / 16;
#pragma unroll 1
    for (int it = 0; it < NIT; ++it) {
        int cur = it & 1;
        bool more = (it + 1) < NIT;
        if (more) GM_LOAD((it + 1) * 16);
        int sb = cur * GM_STAGE;
#pragma unroll
        for (int ch = 0; ch < 2; ++ch) {
            float4 qa[2][2];
#pragma unroll
            for (int mt = 0; mt < 2; ++mt) {
                int r = mb + mt * 16 + g;
                qa[mt][0] = *(const float4*)(sm + sb + ch * 2560 + r * 20 + t4 * 4);
                qa[mt][1] = *(const float4*)(sm + sb + ch * 2560 + (r + 8) * 20 + t4 * 4);
            }
#pragma unroll
            for (int nt = 0; nt < 8; ++nt) {
                int n = nb + nt * 8 + g;
                float4 qb = *(const float4*)(sm + sb + 5120 + ch * 2560 + n * 20 + t4 * 4);
#pragma unroll
                for (int mt = 0; mt < 2; ++mt) {
                    mma8(acc[mt][nt], qa[mt][0].x, qa[mt][1].x, qa[mt][0].y, qa[mt][1].y,
                         qb.x, qb.y);                                         // hi*hi
                    mma8(acc[mt][nt], qa[mt][0].z, qa[mt][1].z, qa[mt][0].w, qa[mt][1].w,
                         qb.x, qb.y);                                         // lo*hi
                    mma8(acc[mt][nt], qa[mt][0].x, qa[mt][1].x, qa[mt][0].y, qa[mt][1].y,
                         qb.z, qb.w);                                         // hi*lo
                }
            }
        }
        if (more) GM_STORE(cur ^ 1);
        __syncthreads();
    }

#pragma unroll
    for (int mt = 0; mt < 2; ++mt) {
        int r = m0 + mb + mt * 16 + g;
#pragma unroll
        for (int nt = 0; nt < 8; ++nt) {
            int n = n0 + nb + nt * 8 + t4 * 2;
            float b0v = bias[n], b1v = bias[n + 1];
            *(float2*)(Z + (size_t)r * NHID + n) =
                make_float2(acc[mt][nt][0] + b0v, acc[mt][nt][1] + b1v);
            *(float2*)(Z + (size_t)(r + 8) * NHID + n) =
                make_float2(acc[mt][nt][2] + b0v, acc[mt][nt][3] + b1v);
        }
    }
#undef GM_LOAD
#undef GM_STORE
}

// per-column BN stats over batch, coalesced
template <int MODE>
__global__ void k_colstats(const float* __restrict__ g, const float* __restrict__ bt) {
    const float* Z = (MODE == 0) ? g_z1 : g_z2;
    float* sc = (MODE == 0) ? g_s1 : g_s2;
    float* sh = (MODE == 0) ? g_sh1 : g_sh2;
    __shared__ double rs[8][32], rq[8][32];
    int tid = threadIdx.x;
    int col = blockIdx.x * 32 + (tid & 31);
    int part = tid >> 5;
    double s = 0.0, q = 0.0;
    for (int bb = part * 512; bb < part * 512 + 512; ++bb) {
        float v = Z[(size_t)bb * NHID + col];
        s += (double)v;
        q += (double)v * (double)v;
    }
    rs[part][tid & 31] = s;
    rq[part][tid & 31] = q;
    __syncthreads();
    if (part == 0) {
        double S = 0.0, Q2 = 0.0;
#pragma unroll
        for (int p2 = 0; p2 < 8; ++p2) { S += rs[p2][tid]; Q2 += rq[p2][tid]; }
        double m = S * (1.0 / NB);
        double var = Q2 * (1.0 / NB) - m * m;
        if (var < 0.0) var = 0.0;
        float inv = (float)(1.0 / sqrt(var + (double)BNEPS));
        float scv = g[col] * inv;
        sc[col] = scv;
        sh[col] = bt[col] - (float)m * scv;
    }
}

__global__ void k_final(const float* __restrict__ wout, const float* __restrict__ bout,
                        float* __restrict__ out) {
    __shared__ float r[128];
    int b = blockIdx.x, tid = threadIdx.x;
    float acc = 0.f;
    for (int j = tid; j < NHID; j += 128) {
        float h = fmaxf(fmaf(g_z2[(size_t)b * NHID + j], g_s2[j], g_sh2[j]), 0.f);
        acc += h * wout[j];
    }
    r[tid] = acc;
    __syncthreads();
    for (int off = 64; off; off >>= 1) {
        if (tid < off) r[tid] += r[tid + off];
        __syncthreads();
    }
    if (tid == 0) out[b] = r[0] + bout[0];
}

// ---------------- launch ----------------
extern "C" void kernel_launch(void* const* d_in, const int* in_sizes, int n_in,
                              void* d_out, int out_size) {
    const int*   x_id    = (const int*)d_in[0];
    const float* x_value = (const float*)d_in[1];
    const float* emb     = (const float*)d_in[2];
    const float* emb_g   = (const float*)d_in[3];
    const float* emb_b   = (const float*)d_in[4];
    const float* Q       = (const float*)d_in[5];
    const float* bil     = (const float*)d_in[6];
    const float* vals    = (const float*)d_in[7];
    const float* arm_g   = (const float*)d_in[8];
    const float* arm_b   = (const float*)d_in[9];
    const float* w1      = (const float*)d_in[10];
    const float* b1      = (const float*)d_in[11];
    const float* g1      = (const float*)d_in[12];
    const float* bt1     = (const float*)d_in[13];
    const float* w2      = (const float*)d_in[14];
    const float* b2      = (const float*)d_in[15];
    const float* g2      = (const float*)d_in[16];
    const float* bt2     = (const float*)d_in[17];
    const float* wout    = (const float*)d_in[18];
    const float* bout    = (const float*)d_in[19];
    float* out = (float*)d_out;

    cudaFuncSetAttribute(k_gemm<ND0, 0>, cudaFuncAttributeMaxDynamicSharedMemorySize, GM_SMEMB);
    cudaFuncSetAttribute(k_gemm<NHID, 1>, cudaFuncAttributeMaxDynamicSharedMemorySize, GM_SMEMB);

    k_zero<<<1, 64>>>();
    k_embed<<<NB, NF>>>(x_id, x_value, emb);
    k_kqef<<<16, 256>>>(bil, Q, emb_g, emb_b);
    k_main<<<NB * NK, 256>>>(vals);
    k_armstats<<<NCH, 256>>>(arm_g, arm_b);
    k_gemm<ND0, 0><<<dim3(NB / 128, NHID / 128), 256, GM_SMEMB>>>(w1, b1);
    k_colstats<0><<<NHID / 32, 256>>>(g1, bt1);
    k_gemm<NHID, 1><<<dim3(NB / 128, NHID / 128), 256, GM_SMEMB>>>(w2, b2);
    k_colstats<1><<<NHID / 32, 256>>>(g2, bt2);
    k_final<<<NB, 128>>>(wout, bout, out);
}